// round 2
// baseline (speedup 1.0000x reference)
#include <cuda_runtime.h>
#include <cuda_bf16.h>
#include <math.h>

#define Bv 4
#define Sv 1024
#define Dv 1024
#define Hv 16
#define Lv 12
#define Cv 8192
#define FFv 4096
#define HDv 64
#define Mv (Bv*Sv)      // 4096 rows
#define PADTOK 2

// ---------------- scratch (static device globals; no allocation) -------------
__device__ float g_x[Mv*Dv];        // residual stream
__device__ float g_h[Mv*Dv];        // layernorm output
__device__ float g_q[Mv*Dv];
__device__ float g_k[Mv*Dv];
__device__ float g_v[Mv*Dv];
__device__ float g_y[Mv*Dv];        // attention output
__device__ float g_ff[Mv*FFv];      // FFN intermediate
__device__ float g_logits[(size_t)Mv*Cv];

// ---------------- embedding + positional encoding ----------------------------
__global__ void embed_kernel(const int* __restrict__ tokens,
                             const float* __restrict__ emb,
                             const float* __restrict__ pe,
                             float* __restrict__ x)
{
    int idx = blockIdx.x * blockDim.x + threadIdx.x;   // over Mv*Dv
    if (idx >= Mv*Dv) return;
    int d  = idx & (Dv-1);
    int ms = idx >> 10;           // row = b*S+s
    int s  = ms & (Sv-1);
    int t  = tokens[ms];
    x[idx] = emb[(size_t)t*Dv + d] * 32.0f + pe[(size_t)s*Dv + d];  // sqrt(D)=32
}

// ---------------- layernorm --------------------------------------------------
__global__ __launch_bounds__(256) void ln_kernel(const float* __restrict__ x,
                                                 const float* __restrict__ g,
                                                 const float* __restrict__ b,
                                                 float* __restrict__ out)
{
    __shared__ float sred[2][8];
    int row = blockIdx.x;
    const float* xr = x + (size_t)row * Dv;
    float s = 0.f, s2 = 0.f;
    for (int i = threadIdx.x; i < Dv; i += 256) {
        float v = xr[i]; s += v; s2 = fmaf(v, v, s2);
    }
    #pragma unroll
    for (int o = 16; o; o >>= 1) {
        s  += __shfl_xor_sync(0xffffffffu, s,  o);
        s2 += __shfl_xor_sync(0xffffffffu, s2, o);
    }
    int w = threadIdx.x >> 5;
    if ((threadIdx.x & 31) == 0) { sred[0][w] = s; sred[1][w] = s2; }
    __syncthreads();
    if (threadIdx.x < 32) {
        s  = (threadIdx.x < 8) ? sred[0][threadIdx.x] : 0.f;
        s2 = (threadIdx.x < 8) ? sred[1][threadIdx.x] : 0.f;
        #pragma unroll
        for (int o = 4; o; o >>= 1) {
            s  += __shfl_xor_sync(0xffffffffu, s,  o);
            s2 += __shfl_xor_sync(0xffffffffu, s2, o);
        }
        if (threadIdx.x == 0) { sred[0][0] = s; sred[1][0] = s2; }
    }
    __syncthreads();
    float mu  = sred[0][0] * (1.0f/Dv);
    float var = sred[1][0] * (1.0f/Dv) - mu*mu;
    float inv = rsqrtf(var + 1e-5f);
    float* orow = out + (size_t)row * Dv;
    for (int i = threadIdx.x; i < Dv; i += 256)
        orow[i] = (xr[i]-mu)*inv*g[i] + b[i];
}

// ---------------- SGEMM: C[m,n] = sum_k A[m,k]*B[n,k] + bias[n] (+epilogue) --
// mode 0: +bias   mode 1: +bias then GELU(exact)   mode 2: +bias + res[m,n]
#define BM 128
#define BN 128
#define BK 8
#define TM 8
#define TN 8
__global__ __launch_bounds__(256) void sgemm_kernel(
    const float* __restrict__ A, const float* __restrict__ Bm,
    const float* __restrict__ bias, const float* __restrict__ res,
    float* __restrict__ Cc, int Mr, int Nr, int Kr, int mode)
{
    __shared__ float As[BK][BM];
    __shared__ float Bs[BK][BN];
    int tid = threadIdx.x;
    int row0 = blockIdx.y * BM;
    int col0 = blockIdx.x * BN;
    int tx = tid & 15, ty = tid >> 4;

    float acc[TM][TN];
    #pragma unroll
    for (int i = 0; i < TM; i++)
        #pragma unroll
        for (int j = 0; j < TN; j++) acc[i][j] = 0.f;

    int la_r = tid >> 1;            // 0..127
    int la_k = (tid & 1) * 4;       // 0 or 4
    const float* Aptr = A  + (size_t)(row0 + la_r) * Kr + la_k;
    const float* Bptr = Bm + (size_t)(col0 + la_r) * Kr + la_k;

    for (int k0 = 0; k0 < Kr; k0 += BK) {
        float4 av = *(const float4*)(Aptr + k0);
        float4 bv = *(const float4*)(Bptr + k0);
        As[la_k+0][la_r] = av.x; As[la_k+1][la_r] = av.y;
        As[la_k+2][la_r] = av.z; As[la_k+3][la_r] = av.w;
        Bs[la_k+0][la_r] = bv.x; Bs[la_k+1][la_r] = bv.y;
        Bs[la_k+2][la_r] = bv.z; Bs[la_k+3][la_r] = bv.w;
        __syncthreads();
        #pragma unroll
        for (int kk = 0; kk < BK; kk++) {
            float a[TM], b[TN];
            #pragma unroll
            for (int i = 0; i < TM; i++) a[i] = As[kk][ty*TM + i];
            #pragma unroll
            for (int j = 0; j < TN; j++) b[j] = Bs[kk][tx*TN + j];
            #pragma unroll
            for (int i = 0; i < TM; i++)
                #pragma unroll
                for (int j = 0; j < TN; j++)
                    acc[i][j] = fmaf(a[i], b[j], acc[i][j]);
        }
        __syncthreads();
    }

    #pragma unroll
    for (int i = 0; i < TM; i++) {
        int m = row0 + ty*TM + i;
        #pragma unroll
        for (int j = 0; j < TN; j++) {
            int n = col0 + tx*TN + j;
            float v = acc[i][j] + bias[n];
            if (mode == 1) v = v * normcdff(v);               // exact GELU
            if (mode == 2) v += res[(size_t)m * Nr + n];      // residual add
            Cc[(size_t)m * Nr + n] = v;
        }
    }
}

// ---------------- causal flash attention (1 thread = 1 query row) ------------
#define KT 32
__global__ __launch_bounds__(128, 1) void attn_kernel(
    const float* __restrict__ q, const float* __restrict__ k,
    const float* __restrict__ v, float* __restrict__ y)
{
    __shared__ float Ks[KT][HDv];
    __shared__ float Vs[KT][HDv];
    int b = blockIdx.z, h = blockIdx.y;
    int qr = blockIdx.x * 128 + threadIdx.x;     // query row in [0,S)
    const float scale = 0.125f;                  // 1/sqrt(HD)

    float qreg[HDv], acc[HDv];
    {
        const float* qp = q + ((size_t)(b*Sv + qr))*Dv + h*HDv;
        #pragma unroll
        for (int d = 0; d < HDv; d++) { qreg[d] = qp[d] * scale; acc[d] = 0.f; }
    }
    float mrow = -1e30f, lrow = 0.f;
    int kmax = blockIdx.x * 128 + 127;           // last key any thread in block needs

    for (int k0 = 0; k0 <= kmax; k0 += KT) {
        __syncthreads();
        for (int idx = threadIdx.x; idx < KT*HDv; idx += 128) {
            int j = idx >> 6, d = idx & 63;
            size_t off = ((size_t)(b*Sv + k0 + j))*Dv + h*HDv + d;
            Ks[j][d] = k[off];
            Vs[j][d] = v[off];
        }
        __syncthreads();

        int jlim = qr - k0 + 1;
        if (jlim <= 0) continue;
        if (jlim > KT) jlim = KT;

        float sarr[KT];
        for (int j = 0; j < jlim; j++) {
            const float4* Kr4 = (const float4*)Ks[j];
            float s0=0.f, s1=0.f, s2=0.f, s3=0.f;
            #pragma unroll
            for (int d4 = 0; d4 < HDv/4; d4++) {
                float4 kv = Kr4[d4];
                s0 = fmaf(qreg[4*d4+0], kv.x, s0);
                s1 = fmaf(qreg[4*d4+1], kv.y, s1);
                s2 = fmaf(qreg[4*d4+2], kv.z, s2);
                s3 = fmaf(qreg[4*d4+3], kv.w, s3);
            }
            sarr[j] = (s0+s1) + (s2+s3);
        }
        float tmax = mrow;
        for (int j = 0; j < jlim; j++) tmax = fmaxf(tmax, sarr[j]);
        float corr = __expf(mrow - tmax);
        lrow *= corr;
        #pragma unroll
        for (int d = 0; d < HDv; d++) acc[d] *= corr;
        mrow = tmax;
        for (int j = 0; j < jlim; j++) {
            float p = __expf(sarr[j] - tmax);
            lrow += p;
            const float4* Vr4 = (const float4*)Vs[j];
            #pragma unroll
            for (int d4 = 0; d4 < HDv/4; d4++) {
                float4 vv = Vr4[d4];
                acc[4*d4+0] = fmaf(p, vv.x, acc[4*d4+0]);
                acc[4*d4+1] = fmaf(p, vv.y, acc[4*d4+1]);
                acc[4*d4+2] = fmaf(p, vv.z, acc[4*d4+2]);
                acc[4*d4+3] = fmaf(p, vv.w, acc[4*d4+3]);
            }
        }
    }
    float invl = 1.0f / lrow;
    float* yp = y + ((size_t)(b*Sv + qr))*Dv + h*HDv;
    #pragma unroll
    for (int d = 0; d < HDv; d++) yp[d] = acc[d] * invl;
}

// ---------------- final loss: log_softmax gather + masked batch sum ----------
__global__ void zero_out_kernel(float* out) {
    if (threadIdx.x < Bv) out[threadIdx.x] = 0.f;
}

__global__ __launch_bounds__(256) void loss_kernel(const float* __restrict__ logits,
                                                   const int* __restrict__ tokens,
                                                   float* __restrict__ out)
{
    __shared__ float sred[8];
    int row = blockIdx.x;                 // b*S+s
    const float* lr = logits + (size_t)row * Cv;

    float mx = -1e30f;
    for (int i = threadIdx.x; i < Cv; i += 256) mx = fmaxf(mx, lr[i]);
    #pragma unroll
    for (int o = 16; o; o >>= 1) mx = fmaxf(mx, __shfl_xor_sync(0xffffffffu, mx, o));
    if ((threadIdx.x & 31) == 0) sred[threadIdx.x >> 5] = mx;
    __syncthreads();
    if (threadIdx.x < 32) {
        mx = (threadIdx.x < 8) ? sred[threadIdx.x] : -1e30f;
        #pragma unroll
        for (int o = 4; o; o >>= 1) mx = fmaxf(mx, __shfl_xor_sync(0xffffffffu, mx, o));
        if (threadIdx.x == 0) sred[0] = mx;
    }
    __syncthreads();
    mx = sred[0];
    __syncthreads();

    float sum = 0.f;
    for (int i = threadIdx.x; i < Cv; i += 256) sum += __expf(lr[i] - mx);
    #pragma unroll
    for (int o = 16; o; o >>= 1) sum += __shfl_xor_sync(0xffffffffu, sum, o);
    if ((threadIdx.x & 31) == 0) sred[threadIdx.x >> 5] = sum;
    __syncthreads();
    if (threadIdx.x < 32) {
        sum = (threadIdx.x < 8) ? sred[threadIdx.x] : 0.f;
        #pragma unroll
        for (int o = 4; o; o >>= 1) sum += __shfl_xor_sync(0xffffffffu, sum, o);
        if (threadIdx.x == 0) {
            int t = tokens[row];
            if (t != PADTOK) {
                float lp = lr[t] - mx - logf(sum);
                atomicAdd(&out[row / Sv], lp);
            }
        }
    }
}

// ---------------- driver -----------------------------------------------------
static void run_gemm(const float* A, const float* W, const float* bias,
                     const float* res, float* Cc, int M_, int N_, int K_, int mode)
{
    dim3 grid(N_/BN, M_/BM);
    sgemm_kernel<<<grid, 256>>>(A, W, bias, res, Cc, M_, N_, K_, mode);
}

extern "C" void kernel_launch(void* const* d_in, const int* in_sizes, int n_in,
                              void* d_out, int out_size)
{
    const int*   tokens = (const int*)  d_in[0];
    const float* emb    = (const float*)d_in[1];
    const float* pe     = (const float*)d_in[2];
    const float* ln1_g  = (const float*)d_in[3];
    const float* ln1_b  = (const float*)d_in[4];
    const float* Wq     = (const float*)d_in[5];
    const float* bq     = (const float*)d_in[6];
    const float* Wk     = (const float*)d_in[7];
    const float* bk     = (const float*)d_in[8];
    const float* Wv     = (const float*)d_in[9];
    const float* bv     = (const float*)d_in[10];
    const float* Wo     = (const float*)d_in[11];
    const float* bo     = (const float*)d_in[12];
    const float* ln2_g  = (const float*)d_in[13];
    const float* ln2_b  = (const float*)d_in[14];
    const float* W1     = (const float*)d_in[15];
    const float* b1     = (const float*)d_in[16];
    const float* W2     = (const float*)d_in[17];
    const float* b2     = (const float*)d_in[18];
    const float* lnf_g  = (const float*)d_in[19];
    const float* lnf_b  = (const float*)d_in[20];
    const float* fcW    = (const float*)d_in[21];
    const float* fcb    = (const float*)d_in[22];
    float* out = (float*)d_out;

    float *x, *h, *q, *k, *v, *y, *ff, *logits;
    cudaGetSymbolAddress((void**)&x,  g_x);
    cudaGetSymbolAddress((void**)&h,  g_h);
    cudaGetSymbolAddress((void**)&q,  g_q);
    cudaGetSymbolAddress((void**)&k,  g_k);
    cudaGetSymbolAddress((void**)&v,  g_v);
    cudaGetSymbolAddress((void**)&y,  g_y);
    cudaGetSymbolAddress((void**)&ff, g_ff);
    cudaGetSymbolAddress((void**)&logits, g_logits);

    // x = emb[tokens]*sqrt(D) + pe
    embed_kernel<<<(Mv*Dv + 255)/256, 256>>>(tokens, emb, pe, x);

    for (int i = 0; i < Lv; i++) {
        const float* wq = Wq + (size_t)i*Dv*Dv;
        const float* wk = Wk + (size_t)i*Dv*Dv;
        const float* wv = Wv + (size_t)i*Dv*Dv;
        const float* wo = Wo + (size_t)i*Dv*Dv;
        const float* w1 = W1 + (size_t)i*FFv*Dv;
        const float* w2 = W2 + (size_t)i*Dv*FFv;

        ln_kernel<<<Mv, 256>>>(x, ln1_g + i*Dv, ln1_b + i*Dv, h);
        run_gemm(h, wq, bq + i*Dv, nullptr, q, Mv, Dv, Dv, 0);
        run_gemm(h, wk, bk + i*Dv, nullptr, k, Mv, Dv, Dv, 0);
        run_gemm(h, wv, bv + i*Dv, nullptr, v, Mv, Dv, Dv, 0);

        dim3 agrid(Sv/128, Hv, Bv);
        attn_kernel<<<agrid, 128>>>(q, k, v, y);

        run_gemm(y, wo, bo + i*Dv, x, x, Mv, Dv, Dv, 2);   // x += proj(y)

        ln_kernel<<<Mv, 256>>>(x, ln2_g + i*Dv, ln2_b + i*Dv, h);
        run_gemm(h, w1, b1 + i*FFv, nullptr, ff, Mv, FFv, Dv, 1);  // GELU
        run_gemm(ff, w2, b2 + i*Dv, x, x, Mv, Dv, FFv, 2);          // x += ffn
    }

    ln_kernel<<<Mv, 256>>>(x, lnf_g, lnf_b, h);
    run_gemm(h, fcW, fcb, nullptr, logits, Mv, Cv, Dv, 0);

    zero_out_kernel<<<1, 32>>>(out);
    loss_kernel<<<Mv, 256>>>(logits, tokens, out);
}

// round 3
// speedup vs baseline: 3.3919x; 3.3919x over previous
#include <cuda_runtime.h>
#include <cuda_bf16.h>
#include <math.h>
#include <stdint.h>

#define Bv 4
#define Sv 1024
#define Dv 1024
#define Hv 16
#define Lv 12
#define Cv 8192
#define FFv 4096
#define HDv 64
#define Mv (Bv*Sv)      // 4096 rows
#define PADTOK 2

// ---------------- scratch (static device globals; no allocation) -------------
__device__ float g_x[Mv*Dv];                    // residual stream (fp32)
__device__ __nv_bfloat16 g_h[Mv*Dv];            // layernorm output (bf16 GEMM input)
__device__ float g_q[Mv*Dv];
__device__ float g_k[Mv*Dv];
__device__ float g_v[Mv*Dv];
__device__ __nv_bfloat16 g_y[Mv*Dv];            // attention output (bf16)
__device__ __nv_bfloat16 g_ff[(size_t)Mv*FFv];  // FFN intermediate (bf16)
__device__ float g_logits[(size_t)Mv*Cv];

// bf16 weight copies
__device__ __nv_bfloat16 g_Wq[(size_t)Lv*Dv*Dv];
__device__ __nv_bfloat16 g_Wk[(size_t)Lv*Dv*Dv];
__device__ __nv_bfloat16 g_Wv[(size_t)Lv*Dv*Dv];
__device__ __nv_bfloat16 g_Wo[(size_t)Lv*Dv*Dv];
__device__ __nv_bfloat16 g_W1[(size_t)Lv*FFv*Dv];
__device__ __nv_bfloat16 g_W2[(size_t)Lv*Dv*FFv];
__device__ __nv_bfloat16 g_fcW[(size_t)Cv*Dv];

// ---------------- fp32 -> bf16 conversion ------------------------------------
__global__ void f2bf_kernel(const float4* __restrict__ in,
                            __nv_bfloat162* __restrict__ out, int n4)
{
    int i = blockIdx.x * blockDim.x + threadIdx.x;
    if (i >= n4) return;
    float4 v = in[i];
    out[2*i]   = __floats2bfloat162_rn(v.x, v.y);
    out[2*i+1] = __floats2bfloat162_rn(v.z, v.w);
}

// ---------------- embedding + positional encoding ----------------------------
__global__ void embed_kernel(const int* __restrict__ tokens,
                             const float* __restrict__ emb,
                             const float* __restrict__ pe,
                             float* __restrict__ x)
{
    int idx = blockIdx.x * blockDim.x + threadIdx.x;
    if (idx >= Mv*Dv) return;
    int d  = idx & (Dv-1);
    int ms = idx >> 10;
    int s  = ms & (Sv-1);
    int t  = tokens[ms];
    x[idx] = emb[(size_t)t*Dv + d] * 32.0f + pe[(size_t)s*Dv + d];
}

// ---------------- layernorm (fp32 in -> bf16 out) ----------------------------
__global__ __launch_bounds__(256) void ln_kernel(const float* __restrict__ x,
                                                 const float* __restrict__ g,
                                                 const float* __restrict__ b,
                                                 __nv_bfloat16* __restrict__ out)
{
    __shared__ float sred[2][8];
    int row = blockIdx.x;
    const float* xr = x + (size_t)row * Dv;
    float s = 0.f, s2 = 0.f;
    for (int i = threadIdx.x; i < Dv; i += 256) {
        float v = xr[i]; s += v; s2 = fmaf(v, v, s2);
    }
    #pragma unroll
    for (int o = 16; o; o >>= 1) {
        s  += __shfl_xor_sync(0xffffffffu, s,  o);
        s2 += __shfl_xor_sync(0xffffffffu, s2, o);
    }
    int w = threadIdx.x >> 5;
    if ((threadIdx.x & 31) == 0) { sred[0][w] = s; sred[1][w] = s2; }
    __syncthreads();
    if (threadIdx.x < 32) {
        s  = (threadIdx.x < 8) ? sred[0][threadIdx.x] : 0.f;
        s2 = (threadIdx.x < 8) ? sred[1][threadIdx.x] : 0.f;
        #pragma unroll
        for (int o = 4; o; o >>= 1) {
            s  += __shfl_xor_sync(0xffffffffu, s,  o);
            s2 += __shfl_xor_sync(0xffffffffu, s2, o);
        }
        if (threadIdx.x == 0) { sred[0][0] = s; sred[1][0] = s2; }
    }
    __syncthreads();
    float mu  = sred[0][0] * (1.0f/Dv);
    float var = sred[1][0] * (1.0f/Dv) - mu*mu;
    float inv = rsqrtf(var + 1e-5f);
    __nv_bfloat16* orow = out + (size_t)row * Dv;
    for (int i = threadIdx.x; i < Dv; i += 256)
        orow[i] = __float2bfloat16((xr[i]-mu)*inv*g[i] + b[i]);
}

// ---------------- bf16 tensor-core GEMM --------------------------------------
// C[m,n] = sum_k A[m,k]*B[n,k] + bias[n] (+epilogue)
// A: bf16 row-major (K contiguous), B: bf16 [N][K] (K contiguous)
// mode 0: +bias -> f32   mode 1: +bias, GELU -> bf16   mode 2: +bias+res -> f32
#define GBM 128
#define GBN 128
#define GBK 32
#define PADK 40   // padded smem row stride (bf16 elems) -> 80B, conflict-free

__device__ __forceinline__ void cp16(void* s, const void* g) {
    uint32_t sa = (uint32_t)__cvta_generic_to_shared(s);
    asm volatile("cp.async.cg.shared.global [%0], [%1], 16;\n" :: "r"(sa), "l"(g));
}
__device__ __forceinline__ void ldsm4(uint32_t* r, const void* p) {
    uint32_t a = (uint32_t)__cvta_generic_to_shared(p);
    asm volatile("ldmatrix.sync.aligned.m8n8.x4.shared.b16 {%0,%1,%2,%3}, [%4];"
        : "=r"(r[0]), "=r"(r[1]), "=r"(r[2]), "=r"(r[3]) : "r"(a));
}
__device__ __forceinline__ void mma16816(float* c, const uint32_t* a, const uint32_t* b) {
    asm volatile("mma.sync.aligned.m16n8k16.row.col.f32.bf16.bf16.f32 "
        "{%0,%1,%2,%3}, {%4,%5,%6,%7}, {%8,%9}, {%0,%1,%2,%3};"
        : "+f"(c[0]), "+f"(c[1]), "+f"(c[2]), "+f"(c[3])
        : "r"(a[0]), "r"(a[1]), "r"(a[2]), "r"(a[3]), "r"(b[0]), "r"(b[1]));
}

__global__ __launch_bounds__(256) void hgemm_kernel(
    const __nv_bfloat16* __restrict__ A, const __nv_bfloat16* __restrict__ Bw,
    const float* __restrict__ bias, const float* __restrict__ res,
    void* __restrict__ Cc, int Mr, int Nr, int Kr, int mode)
{
    __shared__ __nv_bfloat16 As[2][GBM*PADK];
    __shared__ __nv_bfloat16 Bs[2][GBN*PADK];

    int tid  = threadIdx.x;
    int warp = tid >> 5;
    int lane = tid & 31;
    int warp_m = warp & 1;   // 2 tiles of 64 rows
    int warp_n = warp >> 1;  // 4 tiles of 32 cols
    int row0 = blockIdx.y * GBM;
    int col0 = blockIdx.x * GBN;

    float acc[4][4][4];
    #pragma unroll
    for (int i = 0; i < 4; i++)
        #pragma unroll
        for (int j = 0; j < 4; j++)
            #pragma unroll
            for (int t = 0; t < 4; t++) acc[i][j][t] = 0.f;

    // load indices: 512 chunks of 16B (8 bf16) per matrix per stage; 2 per thread
    int c0 = tid, c1 = tid + 256;
    int r0c = c0 >> 2, k0c = (c0 & 3) * 8;
    int r1c = c1 >> 2, k1c = (c1 & 3) * 8;
    const __nv_bfloat16* Ab = A  + (size_t)row0 * Kr;
    const __nv_bfloat16* Bb = Bw + (size_t)col0 * Kr;

    int kt_total = Kr / GBK;

    // prologue: stage 0
    {
        cp16(&As[0][r0c*PADK + k0c], Ab + (size_t)r0c*Kr + k0c);
        cp16(&As[0][r1c*PADK + k1c], Ab + (size_t)r1c*Kr + k1c);
        cp16(&Bs[0][r0c*PADK + k0c], Bb + (size_t)r0c*Kr + k0c);
        cp16(&Bs[0][r1c*PADK + k1c], Bb + (size_t)r1c*Kr + k1c);
        asm volatile("cp.async.commit_group;\n" ::: "memory");
    }

    for (int kt = 0; kt < kt_total; kt++) {
        if (kt + 1 < kt_total) {
            int st = (kt + 1) & 1;
            int kb = (kt + 1) * GBK;
            cp16(&As[st][r0c*PADK + k0c], Ab + (size_t)r0c*Kr + kb + k0c);
            cp16(&As[st][r1c*PADK + k1c], Ab + (size_t)r1c*Kr + kb + k1c);
            cp16(&Bs[st][r0c*PADK + k0c], Bb + (size_t)r0c*Kr + kb + k0c);
            cp16(&Bs[st][r1c*PADK + k1c], Bb + (size_t)r1c*Kr + kb + k1c);
            asm volatile("cp.async.commit_group;\n" ::: "memory");
            asm volatile("cp.async.wait_group 1;\n" ::: "memory");
        } else {
            asm volatile("cp.async.wait_group 0;\n" ::: "memory");
        }
        __syncthreads();

        const __nv_bfloat16* as = As[kt & 1];
        const __nv_bfloat16* bs = Bs[kt & 1];

        #pragma unroll
        for (int ks = 0; ks < 2; ks++) {
            int kof = ks * 16;
            uint32_t ra[4][4];
            #pragma unroll
            for (int mi = 0; mi < 4; mi++) {
                int rr = warp_m*64 + mi*16 + (lane & 15);
                ldsm4(ra[mi], as + rr*PADK + kof + (lane >> 4)*8);
            }
            uint32_t rb[2][4];
            #pragma unroll
            for (int nj = 0; nj < 2; nj++) {
                int nn = warp_n*32 + nj*16 + (lane & 7) + ((lane & 16) >> 1);
                ldsm4(rb[nj], bs + nn*PADK + kof + ((lane >> 3) & 1)*8);
            }
            #pragma unroll
            for (int mi = 0; mi < 4; mi++)
                #pragma unroll
                for (int nt = 0; nt < 4; nt++)
                    mma16816(acc[mi][nt], ra[mi], &rb[nt >> 1][(nt & 1)*2]);
        }
        __syncthreads();
    }

    // epilogue
    #pragma unroll
    for (int mi = 0; mi < 4; mi++) {
        int rw = row0 + warp_m*64 + mi*16 + (lane >> 2);
        #pragma unroll
        for (int nt = 0; nt < 4; nt++) {
            int cw = col0 + warp_n*32 + nt*8 + (lane & 3)*2;
            float2 bb = *(const float2*)(bias + cw);
            float v0 = acc[mi][nt][0] + bb.x;
            float v1 = acc[mi][nt][1] + bb.y;
            float v2 = acc[mi][nt][2] + bb.x;
            float v3 = acc[mi][nt][3] + bb.y;
            if (mode == 0) {
                float* C = (float*)Cc;
                *(float2*)(C + (size_t)rw*Nr + cw)     = make_float2(v0, v1);
                *(float2*)(C + (size_t)(rw+8)*Nr + cw) = make_float2(v2, v3);
            } else if (mode == 1) {
                v0 = v0 * normcdff(v0); v1 = v1 * normcdff(v1);
                v2 = v2 * normcdff(v2); v3 = v3 * normcdff(v3);
                __nv_bfloat16* C = (__nv_bfloat16*)Cc;
                *(__nv_bfloat162*)(C + (size_t)rw*Nr + cw)     = __floats2bfloat162_rn(v0, v1);
                *(__nv_bfloat162*)(C + (size_t)(rw+8)*Nr + cw) = __floats2bfloat162_rn(v2, v3);
            } else {
                float* C = (float*)Cc;
                float2 r1 = *(const float2*)(res + (size_t)rw*Nr + cw);
                float2 r2 = *(const float2*)(res + (size_t)(rw+8)*Nr + cw);
                *(float2*)(C + (size_t)rw*Nr + cw)     = make_float2(v0 + r1.x, v1 + r1.y);
                *(float2*)(C + (size_t)(rw+8)*Nr + cw) = make_float2(v2 + r2.x, v3 + r2.y);
            }
        }
    }
}

// ---------------- causal flash attention (1 thread = 1 query row) ------------
#define KT 32
__global__ __launch_bounds__(128, 1) void attn_kernel(
    const float* __restrict__ q, const float* __restrict__ k,
    const float* __restrict__ v, __nv_bfloat16* __restrict__ y)
{
    __shared__ float Ks[KT][HDv];
    __shared__ float Vs[KT][HDv];
    int b = blockIdx.z, h = blockIdx.y;
    int qr = blockIdx.x * 128 + threadIdx.x;
    const float scale = 0.125f;

    float qreg[HDv], acc[HDv];
    {
        const float* qp = q + ((size_t)(b*Sv + qr))*Dv + h*HDv;
        #pragma unroll
        for (int d = 0; d < HDv; d++) { qreg[d] = qp[d] * scale; acc[d] = 0.f; }
    }
    float mrow = -1e30f, lrow = 0.f;
    int kmax = blockIdx.x * 128 + 127;

    for (int k0 = 0; k0 <= kmax; k0 += KT) {
        __syncthreads();
        for (int idx = threadIdx.x; idx < KT*HDv; idx += 128) {
            int j = idx >> 6, d = idx & 63;
            size_t off = ((size_t)(b*Sv + k0 + j))*Dv + h*HDv + d;
            Ks[j][d] = k[off];
            Vs[j][d] = v[off];
        }
        __syncthreads();

        int jlim = qr - k0 + 1;
        if (jlim <= 0) continue;
        if (jlim > KT) jlim = KT;

        float sarr[KT];
        for (int j = 0; j < jlim; j++) {
            const float4* Kr4 = (const float4*)Ks[j];
            float s0=0.f, s1=0.f, s2=0.f, s3=0.f;
            #pragma unroll
            for (int d4 = 0; d4 < HDv/4; d4++) {
                float4 kv = Kr4[d4];
                s0 = fmaf(qreg[4*d4+0], kv.x, s0);
                s1 = fmaf(qreg[4*d4+1], kv.y, s1);
                s2 = fmaf(qreg[4*d4+2], kv.z, s2);
                s3 = fmaf(qreg[4*d4+3], kv.w, s3);
            }
            sarr[j] = (s0+s1) + (s2+s3);
        }
        float tmax = mrow;
        for (int j = 0; j < jlim; j++) tmax = fmaxf(tmax, sarr[j]);
        float corr = __expf(mrow - tmax);
        lrow *= corr;
        #pragma unroll
        for (int d = 0; d < HDv; d++) acc[d] *= corr;
        mrow = tmax;
        for (int j = 0; j < jlim; j++) {
            float p = __expf(sarr[j] - tmax);
            lrow += p;
            const float4* Vr4 = (const float4*)Vs[j];
            #pragma unroll
            for (int d4 = 0; d4 < HDv/4; d4++) {
                float4 vv = Vr4[d4];
                acc[4*d4+0] = fmaf(p, vv.x, acc[4*d4+0]);
                acc[4*d4+1] = fmaf(p, vv.y, acc[4*d4+1]);
                acc[4*d4+2] = fmaf(p, vv.z, acc[4*d4+2]);
                acc[4*d4+3] = fmaf(p, vv.w, acc[4*d4+3]);
            }
        }
    }
    float invl = 1.0f / lrow;
    __nv_bfloat16* yp = y + ((size_t)(b*Sv + qr))*Dv + h*HDv;
    #pragma unroll
    for (int d = 0; d < HDv; d++) yp[d] = __float2bfloat16(acc[d] * invl);
}

// ---------------- final loss -------------------------------------------------
__global__ void zero_out_kernel(float* out) {
    if (threadIdx.x < Bv) out[threadIdx.x] = 0.f;
}

__global__ __launch_bounds__(256) void loss_kernel(const float* __restrict__ logits,
                                                   const int* __restrict__ tokens,
                                                   float* __restrict__ out)
{
    __shared__ float sred[8];
    int row = blockIdx.x;
    const float* lr = logits + (size_t)row * Cv;

    float mx = -1e30f;
    for (int i = threadIdx.x; i < Cv; i += 256) mx = fmaxf(mx, lr[i]);
    #pragma unroll
    for (int o = 16; o; o >>= 1) mx = fmaxf(mx, __shfl_xor_sync(0xffffffffu, mx, o));
    if ((threadIdx.x & 31) == 0) sred[threadIdx.x >> 5] = mx;
    __syncthreads();
    if (threadIdx.x < 32) {
        mx = (threadIdx.x < 8) ? sred[threadIdx.x] : -1e30f;
        #pragma unroll
        for (int o = 4; o; o >>= 1) mx = fmaxf(mx, __shfl_xor_sync(0xffffffffu, mx, o));
        if (threadIdx.x == 0) sred[0] = mx;
    }
    __syncthreads();
    mx = sred[0];
    __syncthreads();

    float sum = 0.f;
    for (int i = threadIdx.x; i < Cv; i += 256) sum += __expf(lr[i] - mx);
    #pragma unroll
    for (int o = 16; o; o >>= 1) sum += __shfl_xor_sync(0xffffffffu, sum, o);
    if ((threadIdx.x & 31) == 0) sred[threadIdx.x >> 5] = sum;
    __syncthreads();
    if (threadIdx.x < 32) {
        sum = (threadIdx.x < 8) ? sred[threadIdx.x] : 0.f;
        #pragma unroll
        for (int o = 4; o; o >>= 1) sum += __shfl_xor_sync(0xffffffffu, sum, o);
        if (threadIdx.x == 0) {
            int t = tokens[row];
            if (t != PADTOK) {
                float lp = lr[t] - mx - logf(sum);
                atomicAdd(&out[row / Sv], lp);
            }
        }
    }
}

// ---------------- driver -----------------------------------------------------
static void run_hgemm(const __nv_bfloat16* A, const __nv_bfloat16* W,
                      const float* bias, const float* res,
                      void* Cc, int M_, int N_, int K_, int mode)
{
    dim3 grid(N_/GBN, M_/GBM);
    hgemm_kernel<<<grid, 256>>>(A, W, bias, res, Cc, M_, N_, K_, mode);
}

static void run_f2bf(const float* in, __nv_bfloat16* out, size_t n)
{
    int n4 = (int)(n / 4);
    f2bf_kernel<<<(n4 + 255)/256, 256>>>((const float4*)in, (__nv_bfloat162*)out, n4);
}

extern "C" void kernel_launch(void* const* d_in, const int* in_sizes, int n_in,
                              void* d_out, int out_size)
{
    const int*   tokens = (const int*)  d_in[0];
    const float* emb    = (const float*)d_in[1];
    const float* pe     = (const float*)d_in[2];
    const float* ln1_g  = (const float*)d_in[3];
    const float* ln1_b  = (const float*)d_in[4];
    const float* Wq     = (const float*)d_in[5];
    const float* bq     = (const float*)d_in[6];
    const float* Wk     = (const float*)d_in[7];
    const float* bk     = (const float*)d_in[8];
    const float* Wv     = (const float*)d_in[9];
    const float* bv     = (const float*)d_in[10];
    const float* Wo     = (const float*)d_in[11];
    const float* bo     = (const float*)d_in[12];
    const float* ln2_g  = (const float*)d_in[13];
    const float* ln2_b  = (const float*)d_in[14];
    const float* W1     = (const float*)d_in[15];
    const float* b1     = (const float*)d_in[16];
    const float* W2     = (const float*)d_in[17];
    const float* b2     = (const float*)d_in[18];
    const float* lnf_g  = (const float*)d_in[19];
    const float* lnf_b  = (const float*)d_in[20];
    const float* fcW    = (const float*)d_in[21];
    const float* fcb    = (const float*)d_in[22];
    float* out = (float*)d_out;

    float *x, *q, *k, *v, *logits;
    __nv_bfloat16 *h, *y, *ff;
    __nv_bfloat16 *wq_b, *wk_b, *wv_b, *wo_b, *w1_b, *w2_b, *fcw_b;
    cudaGetSymbolAddress((void**)&x,  g_x);
    cudaGetSymbolAddress((void**)&h,  g_h);
    cudaGetSymbolAddress((void**)&q,  g_q);
    cudaGetSymbolAddress((void**)&k,  g_k);
    cudaGetSymbolAddress((void**)&v,  g_v);
    cudaGetSymbolAddress((void**)&y,  g_y);
    cudaGetSymbolAddress((void**)&ff, g_ff);
    cudaGetSymbolAddress((void**)&logits, g_logits);
    cudaGetSymbolAddress((void**)&wq_b, g_Wq);
    cudaGetSymbolAddress((void**)&wk_b, g_Wk);
    cudaGetSymbolAddress((void**)&wv_b, g_Wv);
    cudaGetSymbolAddress((void**)&wo_b, g_Wo);
    cudaGetSymbolAddress((void**)&w1_b, g_W1);
    cudaGetSymbolAddress((void**)&w2_b, g_W2);
    cudaGetSymbolAddress((void**)&fcw_b, g_fcW);

    // convert weights to bf16
    run_f2bf(Wq, wq_b, (size_t)Lv*Dv*Dv);
    run_f2bf(Wk, wk_b, (size_t)Lv*Dv*Dv);
    run_f2bf(Wv, wv_b, (size_t)Lv*Dv*Dv);
    run_f2bf(Wo, wo_b, (size_t)Lv*Dv*Dv);
    run_f2bf(W1, w1_b, (size_t)Lv*FFv*Dv);
    run_f2bf(W2, w2_b, (size_t)Lv*Dv*FFv);
    run_f2bf(fcW, fcw_b, (size_t)Cv*Dv);

    embed_kernel<<<(Mv*Dv + 255)/256, 256>>>(tokens, emb, pe, x);

    for (int i = 0; i < Lv; i++) {
        const __nv_bfloat16* wq = wq_b + (size_t)i*Dv*Dv;
        const __nv_bfloat16* wk = wk_b + (size_t)i*Dv*Dv;
        const __nv_bfloat16* wv = wv_b + (size_t)i*Dv*Dv;
        const __nv_bfloat16* wo = wo_b + (size_t)i*Dv*Dv;
        const __nv_bfloat16* w1 = w1_b + (size_t)i*FFv*Dv;
        const __nv_bfloat16* w2 = w2_b + (size_t)i*Dv*FFv;

        ln_kernel<<<Mv, 256>>>(x, ln1_g + i*Dv, ln1_b + i*Dv, h);
        run_hgemm(h, wq, bq + i*Dv, nullptr, q, Mv, Dv, Dv, 0);
        run_hgemm(h, wk, bk + i*Dv, nullptr, k, Mv, Dv, Dv, 0);
        run_hgemm(h, wv, bv + i*Dv, nullptr, v, Mv, Dv, Dv, 0);

        dim3 agrid(Sv/128, Hv, Bv);
        attn_kernel<<<agrid, 128>>>(q, k, v, y);

        run_hgemm(y, wo, bo + i*Dv, x, x, Mv, Dv, Dv, 2);       // x += proj(y)

        ln_kernel<<<Mv, 256>>>(x, ln2_g + i*Dv, ln2_b + i*Dv, h);
        run_hgemm(h, w1, b1 + i*FFv, nullptr, ff, Mv, FFv, Dv, 1);  // GELU -> bf16
        run_hgemm(ff, w2, b2 + i*Dv, x, x, Mv, Dv, FFv, 2);          // x += ffn
    }

    ln_kernel<<<Mv, 256>>>(x, lnf_g, lnf_b, h);
    run_hgemm(h, fcw_b, fcb, nullptr, logits, Mv, Cv, Dv, 0);

    zero_out_kernel<<<1, 32>>>(out);
    loss_kernel<<<Mv, 256>>>(logits, tokens, out);
}

// round 4
// speedup vs baseline: 6.4783x; 1.9100x over previous
#include <cuda_runtime.h>
#include <cuda_bf16.h>
#include <math.h>
#include <stdint.h>

#define Bv 4
#define Sv 1024
#define Dv 1024
#define Hv 16
#define Lv 12
#define Cv 8192
#define FFv 4096
#define HDv 64
#define Mv (Bv*Sv)
#define PADTOK 2

// ---------------- scratch ----------------------------------------------------
__device__ float g_x[Mv*Dv];
__device__ __nv_bfloat16 g_h[Mv*Dv];
__device__ __nv_bfloat16 g_qb[Mv*Dv];
__device__ __nv_bfloat16 g_kb[Mv*Dv];
__device__ __nv_bfloat16 g_vb[Mv*Dv];
__device__ __nv_bfloat16 g_y[Mv*Dv];
__device__ __nv_bfloat16 g_ff[(size_t)Mv*FFv];
__device__ float g_logits[(size_t)Mv*Cv];

__device__ __nv_bfloat16 g_Wq[(size_t)Lv*Dv*Dv];
__device__ __nv_bfloat16 g_Wk[(size_t)Lv*Dv*Dv];
__device__ __nv_bfloat16 g_Wv[(size_t)Lv*Dv*Dv];
__device__ __nv_bfloat16 g_Wo[(size_t)Lv*Dv*Dv];
__device__ __nv_bfloat16 g_W1[(size_t)Lv*FFv*Dv];
__device__ __nv_bfloat16 g_W2[(size_t)Lv*Dv*FFv];
__device__ __nv_bfloat16 g_fcW[(size_t)Cv*Dv];

// ---------------- fp32 -> bf16 ------------------------------------------------
__global__ void f2bf_kernel(const float4* __restrict__ in,
                            __nv_bfloat162* __restrict__ out, int n4)
{
    int i = blockIdx.x * blockDim.x + threadIdx.x;
    if (i >= n4) return;
    float4 v = in[i];
    out[2*i]   = __floats2bfloat162_rn(v.x, v.y);
    out[2*i+1] = __floats2bfloat162_rn(v.z, v.w);
}

// ---------------- embedding ---------------------------------------------------
__global__ void embed_kernel(const int* __restrict__ tokens,
                             const float* __restrict__ emb,
                             const float* __restrict__ pe,
                             float* __restrict__ x)
{
    int idx = blockIdx.x * blockDim.x + threadIdx.x;
    if (idx >= Mv*Dv) return;
    int d  = idx & (Dv-1);
    int ms = idx >> 10;
    int s  = ms & (Sv-1);
    int t  = tokens[ms];
    x[idx] = emb[(size_t)t*Dv + d] * 32.0f + pe[(size_t)s*Dv + d];
}

// ---------------- layernorm ---------------------------------------------------
__global__ __launch_bounds__(256) void ln_kernel(const float* __restrict__ x,
                                                 const float* __restrict__ g,
                                                 const float* __restrict__ b,
                                                 __nv_bfloat16* __restrict__ out)
{
    __shared__ float sred[2][8];
    int row = blockIdx.x;
    const float* xr = x + (size_t)row * Dv;
    float s = 0.f, s2 = 0.f;
    for (int i = threadIdx.x; i < Dv; i += 256) {
        float v = xr[i]; s += v; s2 = fmaf(v, v, s2);
    }
    #pragma unroll
    for (int o = 16; o; o >>= 1) {
        s  += __shfl_xor_sync(0xffffffffu, s,  o);
        s2 += __shfl_xor_sync(0xffffffffu, s2, o);
    }
    int w = threadIdx.x >> 5;
    if ((threadIdx.x & 31) == 0) { sred[0][w] = s; sred[1][w] = s2; }
    __syncthreads();
    if (threadIdx.x < 32) {
        s  = (threadIdx.x < 8) ? sred[0][threadIdx.x] : 0.f;
        s2 = (threadIdx.x < 8) ? sred[1][threadIdx.x] : 0.f;
        #pragma unroll
        for (int o = 4; o; o >>= 1) {
            s  += __shfl_xor_sync(0xffffffffu, s,  o);
            s2 += __shfl_xor_sync(0xffffffffu, s2, o);
        }
        if (threadIdx.x == 0) { sred[0][0] = s; sred[1][0] = s2; }
    }
    __syncthreads();
    float mu  = sred[0][0] * (1.0f/Dv);
    float var = sred[1][0] * (1.0f/Dv) - mu*mu;
    float inv = rsqrtf(var + 1e-5f);
    __nv_bfloat16* orow = out + (size_t)row * Dv;
    for (int i = threadIdx.x; i < Dv; i += 256)
        orow[i] = __float2bfloat16((xr[i]-mu)*inv*g[i] + b[i]);
}

// ---------------- MMA helpers -------------------------------------------------
__device__ __forceinline__ void cp16(void* s, const void* g) {
    uint32_t sa = (uint32_t)__cvta_generic_to_shared(s);
    asm volatile("cp.async.cg.shared.global [%0], [%1], 16;\n" :: "r"(sa), "l"(g));
}
__device__ __forceinline__ void ldsm4(uint32_t* r, const void* p) {
    uint32_t a = (uint32_t)__cvta_generic_to_shared(p);
    asm volatile("ldmatrix.sync.aligned.m8n8.x4.shared.b16 {%0,%1,%2,%3}, [%4];"
        : "=r"(r[0]), "=r"(r[1]), "=r"(r[2]), "=r"(r[3]) : "r"(a));
}
__device__ __forceinline__ void ldsm4t(uint32_t* r, const void* p) {
    uint32_t a = (uint32_t)__cvta_generic_to_shared(p);
    asm volatile("ldmatrix.sync.aligned.m8n8.x4.trans.shared.b16 {%0,%1,%2,%3}, [%4];"
        : "=r"(r[0]), "=r"(r[1]), "=r"(r[2]), "=r"(r[3]) : "r"(a));
}
__device__ __forceinline__ void mma16816(float* c, const uint32_t* a, const uint32_t* b) {
    asm volatile("mma.sync.aligned.m16n8k16.row.col.f32.bf16.bf16.f32 "
        "{%0,%1,%2,%3}, {%4,%5,%6,%7}, {%8,%9}, {%0,%1,%2,%3};"
        : "+f"(c[0]), "+f"(c[1]), "+f"(c[2]), "+f"(c[3])
        : "r"(a[0]), "r"(a[1]), "r"(a[2]), "r"(a[3]), "r"(b[0]), "r"(b[1]));
}

// ---------------- bf16 tensor-core GEMM --------------------------------------
// mode 0: +bias->f32  1: +bias,GELU->bf16  2: +bias+res->f32  3: +bias->bf16
#define GBM 128
#define GBN 128
#define GBK 32
#define PADK 40

__global__ __launch_bounds__(256) void hgemm_kernel(
    const __nv_bfloat16* __restrict__ A, const __nv_bfloat16* __restrict__ Bw,
    const float* __restrict__ bias, const float* __restrict__ res,
    void* __restrict__ Cc, int Mr, int Nr, int Kr, int mode)
{
    __shared__ __nv_bfloat16 As[2][GBM*PADK];
    __shared__ __nv_bfloat16 Bs[2][GBN*PADK];

    int tid  = threadIdx.x;
    int warp = tid >> 5;
    int lane = tid & 31;
    int warp_m = warp & 1;
    int warp_n = warp >> 1;
    int row0 = blockIdx.y * GBM;
    int col0 = blockIdx.x * GBN;

    float acc[4][4][4];
    #pragma unroll
    for (int i = 0; i < 4; i++)
        #pragma unroll
        for (int j = 0; j < 4; j++)
            #pragma unroll
            for (int t = 0; t < 4; t++) acc[i][j][t] = 0.f;

    int c0 = tid, c1 = tid + 256;
    int r0c = c0 >> 2, k0c = (c0 & 3) * 8;
    int r1c = c1 >> 2, k1c = (c1 & 3) * 8;
    const __nv_bfloat16* Ab = A  + (size_t)row0 * Kr;
    const __nv_bfloat16* Bb = Bw + (size_t)col0 * Kr;

    int kt_total = Kr / GBK;
    {
        cp16(&As[0][r0c*PADK + k0c], Ab + (size_t)r0c*Kr + k0c);
        cp16(&As[0][r1c*PADK + k1c], Ab + (size_t)r1c*Kr + k1c);
        cp16(&Bs[0][r0c*PADK + k0c], Bb + (size_t)r0c*Kr + k0c);
        cp16(&Bs[0][r1c*PADK + k1c], Bb + (size_t)r1c*Kr + k1c);
        asm volatile("cp.async.commit_group;\n" ::: "memory");
    }

    for (int kt = 0; kt < kt_total; kt++) {
        if (kt + 1 < kt_total) {
            int st = (kt + 1) & 1;
            int kb = (kt + 1) * GBK;
            cp16(&As[st][r0c*PADK + k0c], Ab + (size_t)r0c*Kr + kb + k0c);
            cp16(&As[st][r1c*PADK + k1c], Ab + (size_t)r1c*Kr + kb + k1c);
            cp16(&Bs[st][r0c*PADK + k0c], Bb + (size_t)r0c*Kr + kb + k0c);
            cp16(&Bs[st][r1c*PADK + k1c], Bb + (size_t)r1c*Kr + kb + k1c);
            asm volatile("cp.async.commit_group;\n" ::: "memory");
            asm volatile("cp.async.wait_group 1;\n" ::: "memory");
        } else {
            asm volatile("cp.async.wait_group 0;\n" ::: "memory");
        }
        __syncthreads();

        const __nv_bfloat16* as = As[kt & 1];
        const __nv_bfloat16* bs = Bs[kt & 1];

        #pragma unroll
        for (int ks = 0; ks < 2; ks++) {
            int kof = ks * 16;
            uint32_t ra[4][4];
            #pragma unroll
            for (int mi = 0; mi < 4; mi++) {
                int rr = warp_m*64 + mi*16 + (lane & 15);
                ldsm4(ra[mi], as + rr*PADK + kof + (lane >> 4)*8);
            }
            uint32_t rb[2][4];
            #pragma unroll
            for (int nj = 0; nj < 2; nj++) {
                int nn = warp_n*32 + nj*16 + (lane & 7) + ((lane & 16) >> 1);
                ldsm4(rb[nj], bs + nn*PADK + kof + ((lane >> 3) & 1)*8);
            }
            #pragma unroll
            for (int mi = 0; mi < 4; mi++)
                #pragma unroll
                for (int nt = 0; nt < 4; nt++)
                    mma16816(acc[mi][nt], ra[mi], &rb[nt >> 1][(nt & 1)*2]);
        }
        __syncthreads();
    }

    #pragma unroll
    for (int mi = 0; mi < 4; mi++) {
        int rw = row0 + warp_m*64 + mi*16 + (lane >> 2);
        #pragma unroll
        for (int nt = 0; nt < 4; nt++) {
            int cw = col0 + warp_n*32 + nt*8 + (lane & 3)*2;
            float2 bb = *(const float2*)(bias + cw);
            float v0 = acc[mi][nt][0] + bb.x;
            float v1 = acc[mi][nt][1] + bb.y;
            float v2 = acc[mi][nt][2] + bb.x;
            float v3 = acc[mi][nt][3] + bb.y;
            if (mode == 0) {
                float* C = (float*)Cc;
                *(float2*)(C + (size_t)rw*Nr + cw)     = make_float2(v0, v1);
                *(float2*)(C + (size_t)(rw+8)*Nr + cw) = make_float2(v2, v3);
            } else if (mode == 1) {
                v0 = v0 * normcdff(v0); v1 = v1 * normcdff(v1);
                v2 = v2 * normcdff(v2); v3 = v3 * normcdff(v3);
                __nv_bfloat16* C = (__nv_bfloat16*)Cc;
                *(__nv_bfloat162*)(C + (size_t)rw*Nr + cw)     = __floats2bfloat162_rn(v0, v1);
                *(__nv_bfloat162*)(C + (size_t)(rw+8)*Nr + cw) = __floats2bfloat162_rn(v2, v3);
            } else if (mode == 2) {
                float* C = (float*)Cc;
                float2 r1 = *(const float2*)(res + (size_t)rw*Nr + cw);
                float2 r2 = *(const float2*)(res + (size_t)(rw+8)*Nr + cw);
                *(float2*)(C + (size_t)rw*Nr + cw)     = make_float2(v0 + r1.x, v1 + r1.y);
                *(float2*)(C + (size_t)(rw+8)*Nr + cw) = make_float2(v2 + r2.x, v3 + r2.y);
            } else {
                __nv_bfloat16* C = (__nv_bfloat16*)Cc;
                *(__nv_bfloat162*)(C + (size_t)rw*Nr + cw)     = __floats2bfloat162_rn(v0, v1);
                *(__nv_bfloat162*)(C + (size_t)(rw+8)*Nr + cw) = __floats2bfloat162_rn(v2, v3);
            }
        }
    }
}

// ---------------- MMA flash attention ----------------------------------------
// Block: 64 queries for one (b,h); 4 warps, each warp 16 query rows.
#define AQ 64
#define AK 64
#define APAD 72   // 144B row stride: 16B-aligned, ldmatrix conflict-free

__global__ __launch_bounds__(128) void attn_mma_kernel(
    const __nv_bfloat16* __restrict__ q, const __nv_bfloat16* __restrict__ k,
    const __nv_bfloat16* __restrict__ v, __nv_bfloat16* __restrict__ y)
{
    __shared__ __nv_bfloat16 Qs[AQ][APAD];
    __shared__ __nv_bfloat16 Ks[AK][APAD];
    __shared__ __nv_bfloat16 Vs[AK][APAD];

    int b = blockIdx.z, h = blockIdx.y;
    int q0 = blockIdx.x * AQ;
    int tid = threadIdx.x, wid = tid >> 5, lane = tid & 31;

    // load Q tile (64x64): each thread one half-row of 32 bf16 (4x16B)
    {
        int row = tid >> 1, half = (tid & 1) * 32;
        const uint4* src = (const uint4*)(q + ((size_t)(b*Sv + q0 + row))*Dv + h*HDv + half);
        uint4* dst = (uint4*)&Qs[row][half];
        dst[0] = src[0]; dst[1] = src[1]; dst[2] = src[2]; dst[3] = src[3];
    }

    float m0 = -1e30f, m1 = -1e30f, l0 = 0.f, l1 = 0.f;
    float Oa[8][4];
    #pragma unroll
    for (int i = 0; i < 8; i++)
        #pragma unroll
        for (int j = 0; j < 4; j++) Oa[i][j] = 0.f;

    int r_lo = lane >> 2;          // warp-local rows r_lo, r_lo+8
    int colb = (lane & 3) * 2;

    for (int j0 = 0; j0 <= q0; j0 += AK) {
        // load K,V tile
        __syncthreads();
        {
            int row = tid >> 1, half = (tid & 1) * 32;
            size_t off = ((size_t)(b*Sv + j0 + row))*Dv + h*HDv + half;
            const uint4* ks = (const uint4*)(k + off);
            const uint4* vs = (const uint4*)(v + off);
            uint4* kd = (uint4*)&Ks[row][half];
            uint4* vd = (uint4*)&Vs[row][half];
            kd[0]=ks[0]; kd[1]=ks[1]; kd[2]=ks[2]; kd[3]=ks[3];
            vd[0]=vs[0]; vd[1]=vs[1]; vd[2]=vs[2]; vd[3]=vs[3];
        }
        __syncthreads();

        // S = Q Kt  (16x64 per warp)
        float c[8][4];
        #pragma unroll
        for (int i = 0; i < 8; i++)
            #pragma unroll
            for (int j = 0; j < 4; j++) c[i][j] = 0.f;

        #pragma unroll
        for (int kk = 0; kk < 4; kk++) {
            int kof = kk * 16;
            uint32_t ra[4];
            ldsm4(ra, &Qs[wid*16 + (lane & 15)][kof + (lane >> 4)*8]);
            #pragma unroll
            for (int nt = 0; nt < 4; nt++) {
                uint32_t rb[4];
                int nn = nt*16 + (lane & 7) + ((lane & 16) >> 1);
                ldsm4(rb, &Ks[nn][kof + ((lane >> 3) & 1)*8]);
                mma16816(c[2*nt],   ra, &rb[0]);
                mma16816(c[2*nt+1], ra, &rb[2]);
            }
        }

        // scale + causal mask (diagonal tile only)
        int row0 = q0 + wid*16 + r_lo;
        int row1 = row0 + 8;
        #pragma unroll
        for (int nt = 0; nt < 8; nt++) {
            c[nt][0] *= 0.125f; c[nt][1] *= 0.125f;
            c[nt][2] *= 0.125f; c[nt][3] *= 0.125f;
        }
        if (j0 == q0) {
            #pragma unroll
            for (int nt = 0; nt < 8; nt++) {
                int col = j0 + nt*8 + colb;
                if (col   > row0) c[nt][0] = -1e30f;
                if (col+1 > row0) c[nt][1] = -1e30f;
                if (col   > row1) c[nt][2] = -1e30f;
                if (col+1 > row1) c[nt][3] = -1e30f;
            }
        }

        // row max
        float rm0 = -1e30f, rm1 = -1e30f;
        #pragma unroll
        for (int nt = 0; nt < 8; nt++) {
            rm0 = fmaxf(rm0, fmaxf(c[nt][0], c[nt][1]));
            rm1 = fmaxf(rm1, fmaxf(c[nt][2], c[nt][3]));
        }
        rm0 = fmaxf(rm0, __shfl_xor_sync(0xffffffffu, rm0, 1));
        rm0 = fmaxf(rm0, __shfl_xor_sync(0xffffffffu, rm0, 2));
        rm1 = fmaxf(rm1, __shfl_xor_sync(0xffffffffu, rm1, 1));
        rm1 = fmaxf(rm1, __shfl_xor_sync(0xffffffffu, rm1, 2));

        float mn0 = fmaxf(m0, rm0), mn1 = fmaxf(m1, rm1);
        float cr0 = __expf(m0 - mn0), cr1 = __expf(m1 - mn1);
        m0 = mn0; m1 = mn1;

        float ps0 = 0.f, ps1 = 0.f;
        #pragma unroll
        for (int nt = 0; nt < 8; nt++) {
            c[nt][0] = __expf(c[nt][0] - mn0);
            c[nt][1] = __expf(c[nt][1] - mn0);
            c[nt][2] = __expf(c[nt][2] - mn1);
            c[nt][3] = __expf(c[nt][3] - mn1);
            ps0 += c[nt][0] + c[nt][1];
            ps1 += c[nt][2] + c[nt][3];
        }
        ps0 += __shfl_xor_sync(0xffffffffu, ps0, 1);
        ps0 += __shfl_xor_sync(0xffffffffu, ps0, 2);
        ps1 += __shfl_xor_sync(0xffffffffu, ps1, 1);
        ps1 += __shfl_xor_sync(0xffffffffu, ps1, 2);
        l0 = l0*cr0 + ps0;
        l1 = l1*cr1 + ps1;

        #pragma unroll
        for (int nt = 0; nt < 8; nt++) {
            Oa[nt][0] *= cr0; Oa[nt][1] *= cr0;
            Oa[nt][2] *= cr1; Oa[nt][3] *= cr1;
        }

        // O += P V  (keys in 4 chunks of 16)
        #pragma unroll
        for (int kt = 0; kt < 4; kt++) {
            uint32_t a[4];
            __nv_bfloat162 p0 = __floats2bfloat162_rn(c[2*kt][0],   c[2*kt][1]);
            __nv_bfloat162 p1 = __floats2bfloat162_rn(c[2*kt][2],   c[2*kt][3]);
            __nv_bfloat162 p2 = __floats2bfloat162_rn(c[2*kt+1][0], c[2*kt+1][1]);
            __nv_bfloat162 p3 = __floats2bfloat162_rn(c[2*kt+1][2], c[2*kt+1][3]);
            a[0] = *(uint32_t*)&p0; a[1] = *(uint32_t*)&p1;
            a[2] = *(uint32_t*)&p2; a[3] = *(uint32_t*)&p3;
            #pragma unroll
            for (int nt = 0; nt < 4; nt++) {
                uint32_t rv[4];
                int key = kt*16 + (lane & 7) + ((lane >> 3) & 1)*8;
                int dim = nt*16 + (lane >> 4)*8;
                ldsm4t(rv, &Vs[key][dim]);
                mma16816(Oa[2*nt],   a, &rv[0]);
                mma16816(Oa[2*nt+1], a, &rv[2]);
            }
        }
    }

    // normalize + write
    float il0 = 1.0f / l0, il1 = 1.0f / l1;
    int grow0 = q0 + wid*16 + r_lo;
    #pragma unroll
    for (int nt = 0; nt < 8; nt++) {
        int dcol = nt*8 + colb;
        __nv_bfloat16* yp0 = y + ((size_t)(b*Sv + grow0))*Dv + h*HDv + dcol;
        __nv_bfloat16* yp1 = y + ((size_t)(b*Sv + grow0 + 8))*Dv + h*HDv + dcol;
        *(__nv_bfloat162*)yp0 = __floats2bfloat162_rn(Oa[nt][0]*il0, Oa[nt][1]*il0);
        *(__nv_bfloat162*)yp1 = __floats2bfloat162_rn(Oa[nt][2]*il1, Oa[nt][3]*il1);
    }
}

// ---------------- final loss -------------------------------------------------
__global__ void zero_out_kernel(float* out) {
    if (threadIdx.x < Bv) out[threadIdx.x] = 0.f;
}

__global__ __launch_bounds__(256) void loss_kernel(const float* __restrict__ logits,
                                                   const int* __restrict__ tokens,
                                                   float* __restrict__ out)
{
    __shared__ float sred[8];
    int row = blockIdx.x;
    const float* lr = logits + (size_t)row * Cv;

    float mx = -1e30f;
    for (int i = threadIdx.x; i < Cv; i += 256) mx = fmaxf(mx, lr[i]);
    #pragma unroll
    for (int o = 16; o; o >>= 1) mx = fmaxf(mx, __shfl_xor_sync(0xffffffffu, mx, o));
    if ((threadIdx.x & 31) == 0) sred[threadIdx.x >> 5] = mx;
    __syncthreads();
    if (threadIdx.x < 32) {
        mx = (threadIdx.x < 8) ? sred[threadIdx.x] : -1e30f;
        #pragma unroll
        for (int o = 4; o; o >>= 1) mx = fmaxf(mx, __shfl_xor_sync(0xffffffffu, mx, o));
        if (threadIdx.x == 0) sred[0] = mx;
    }
    __syncthreads();
    mx = sred[0];
    __syncthreads();

    float sum = 0.f;
    for (int i = threadIdx.x; i < Cv; i += 256) sum += __expf(lr[i] - mx);
    #pragma unroll
    for (int o = 16; o; o >>= 1) sum += __shfl_xor_sync(0xffffffffu, sum, o);
    if ((threadIdx.x & 31) == 0) sred[threadIdx.x >> 5] = sum;
    __syncthreads();
    if (threadIdx.x < 32) {
        sum = (threadIdx.x < 8) ? sred[threadIdx.x] : 0.f;
        #pragma unroll
        for (int o = 4; o; o >>= 1) sum += __shfl_xor_sync(0xffffffffu, sum, o);
        if (threadIdx.x == 0) {
            int t = tokens[row];
            if (t != PADTOK) {
                float lp = lr[t] - mx - logf(sum);
                atomicAdd(&out[row / Sv], lp);
            }
        }
    }
}

// ---------------- driver -----------------------------------------------------
static void run_hgemm(const __nv_bfloat16* A, const __nv_bfloat16* W,
                      const float* bias, const float* res,
                      void* Cc, int M_, int N_, int K_, int mode)
{
    dim3 grid(N_/GBN, M_/GBM);
    hgemm_kernel<<<grid, 256>>>(A, W, bias, res, Cc, M_, N_, K_, mode);
}

static void run_f2bf(const float* in, __nv_bfloat16* out, size_t n)
{
    int n4 = (int)(n / 4);
    f2bf_kernel<<<(n4 + 255)/256, 256>>>((const float4*)in, (__nv_bfloat162*)out, n4);
}

extern "C" void kernel_launch(void* const* d_in, const int* in_sizes, int n_in,
                              void* d_out, int out_size)
{
    const int*   tokens = (const int*)  d_in[0];
    const float* emb    = (const float*)d_in[1];
    const float* pe     = (const float*)d_in[2];
    const float* ln1_g  = (const float*)d_in[3];
    const float* ln1_b  = (const float*)d_in[4];
    const float* Wq     = (const float*)d_in[5];
    const float* bq     = (const float*)d_in[6];
    const float* Wk     = (const float*)d_in[7];
    const float* bk     = (const float*)d_in[8];
    const float* Wv     = (const float*)d_in[9];
    const float* bv     = (const float*)d_in[10];
    const float* Wo     = (const float*)d_in[11];
    const float* bo     = (const float*)d_in[12];
    const float* ln2_g  = (const float*)d_in[13];
    const float* ln2_b  = (const float*)d_in[14];
    const float* W1     = (const float*)d_in[15];
    const float* b1     = (const float*)d_in[16];
    const float* W2     = (const float*)d_in[17];
    const float* b2     = (const float*)d_in[18];
    const float* lnf_g  = (const float*)d_in[19];
    const float* lnf_b  = (const float*)d_in[20];
    const float* fcW    = (const float*)d_in[21];
    const float* fcb    = (const float*)d_in[22];
    float* out = (float*)d_out;

    float *x, *logits;
    __nv_bfloat16 *h, *y, *ff, *qb, *kb, *vb;
    __nv_bfloat16 *wq_b, *wk_b, *wv_b, *wo_b, *w1_b, *w2_b, *fcw_b;
    cudaGetSymbolAddress((void**)&x,  g_x);
    cudaGetSymbolAddress((void**)&h,  g_h);
    cudaGetSymbolAddress((void**)&qb, g_qb);
    cudaGetSymbolAddress((void**)&kb, g_kb);
    cudaGetSymbolAddress((void**)&vb, g_vb);
    cudaGetSymbolAddress((void**)&y,  g_y);
    cudaGetSymbolAddress((void**)&ff, g_ff);
    cudaGetSymbolAddress((void**)&logits, g_logits);
    cudaGetSymbolAddress((void**)&wq_b, g_Wq);
    cudaGetSymbolAddress((void**)&wk_b, g_Wk);
    cudaGetSymbolAddress((void**)&wv_b, g_Wv);
    cudaGetSymbolAddress((void**)&wo_b, g_Wo);
    cudaGetSymbolAddress((void**)&w1_b, g_W1);
    cudaGetSymbolAddress((void**)&w2_b, g_W2);
    cudaGetSymbolAddress((void**)&fcw_b, g_fcW);

    run_f2bf(Wq, wq_b, (size_t)Lv*Dv*Dv);
    run_f2bf(Wk, wk_b, (size_t)Lv*Dv*Dv);
    run_f2bf(Wv, wv_b, (size_t)Lv*Dv*Dv);
    run_f2bf(Wo, wo_b, (size_t)Lv*Dv*Dv);
    run_f2bf(W1, w1_b, (size_t)Lv*FFv*Dv);
    run_f2bf(W2, w2_b, (size_t)Lv*Dv*FFv);
    run_f2bf(fcW, fcw_b, (size_t)Cv*Dv);

    embed_kernel<<<(Mv*Dv + 255)/256, 256>>>(tokens, emb, pe, x);

    for (int i = 0; i < Lv; i++) {
        const __nv_bfloat16* wq = wq_b + (size_t)i*Dv*Dv;
        const __nv_bfloat16* wk = wk_b + (size_t)i*Dv*Dv;
        const __nv_bfloat16* wv = wv_b + (size_t)i*Dv*Dv;
        const __nv_bfloat16* wo = wo_b + (size_t)i*Dv*Dv;
        const __nv_bfloat16* w1 = w1_b + (size_t)i*FFv*Dv;
        const __nv_bfloat16* w2 = w2_b + (size_t)i*Dv*FFv;

        ln_kernel<<<Mv, 256>>>(x, ln1_g + i*Dv, ln1_b + i*Dv, h);
        run_hgemm(h, wq, bq + i*Dv, nullptr, qb, Mv, Dv, Dv, 3);
        run_hgemm(h, wk, bk + i*Dv, nullptr, kb, Mv, Dv, Dv, 3);
        run_hgemm(h, wv, bv + i*Dv, nullptr, vb, Mv, Dv, Dv, 3);

        dim3 agrid(Sv/AQ, Hv, Bv);
        attn_mma_kernel<<<agrid, 128>>>(qb, kb, vb, y);

        run_hgemm(y, wo, bo + i*Dv, x, x, Mv, Dv, Dv, 2);

        ln_kernel<<<Mv, 256>>>(x, ln2_g + i*Dv, ln2_b + i*Dv, h);
        run_hgemm(h, w1, b1 + i*FFv, nullptr, ff, Mv, FFv, Dv, 1);
        run_hgemm(ff, w2, b2 + i*Dv, x, x, Mv, Dv, FFv, 2);
    }

    ln_kernel<<<Mv, 256>>>(x, lnf_g, lnf_b, h);
    run_hgemm(h, fcw_b, fcb, nullptr, logits, Mv, Cv, Dv, 0);

    zero_out_kernel<<<1, 32>>>(out);
    loss_kernel<<<Mv, 256>>>(logits, tokens, out);
}